// round 5
// baseline (speedup 1.0000x reference)
#include <cuda_runtime.h>
#include <cstdint>

#define BATCHN 4096
#define INSZ   1024
#define HUN    512
#define GN     2048      // 4*HU
#define SHID   4096      // input state hidden stride
#define OHID   2048      // output state hidden stride (N_DEPTH*HU)

// Scratch (device globals: allocation-free)
__device__ float g_h0[(size_t)4 * BATCHN * HUN];   // h_out of stack 0, per depth
__device__ float g_X2[(size_t)4 * BATCHN * INSZ];  // dec_input for stack 1, per depth

__device__ __forceinline__ uint32_t f2tf32(float x) {
    uint32_t y;
    asm("cvt.rna.tf32.f32 %0, %1;\n" : "=r"(y) : "f"(x));
    return y;
}

__device__ __forceinline__ void mma8(float* c, const uint32_t* a, const uint32_t* b) {
    asm volatile(
        "mma.sync.aligned.m16n8k8.row.col.f32.tf32.tf32.f32 "
        "{%0,%1,%2,%3}, {%4,%5,%6,%7}, {%8,%9}, {%0,%1,%2,%3};\n"
        : "+f"(c[0]), "+f"(c[1]), "+f"(c[2]), "+f"(c[3])
        : "r"(a[0]), "r"(a[1]), "r"(a[2]), "r"(a[3]), "r"(b[0]), "r"(b[1]));
}

__device__ __forceinline__ float sigm(float x) { return 1.f / (1.f + __expf(-x)); }

// ---------------------------------------------------------------------------
// gates kernel: C[128 x 64] tile of gates for (depth d, stack j).
// Block-local column n in [0,64): gate = n/16, hidden h = hblk*16 + n%16.
// GEMM: gates = [X | hx] @ [Wih | Whh]^T  (K = 1024 + 512 = 1536), NT form.
// Epilogue: +biases, LSTM nonlinearity, residual, writes outputs.
// ---------------------------------------------------------------------------
__global__ __launch_bounds__(256, 2) void gates_kernel(
    const float* __restrict__ input, const float* __restrict__ state,
    const float* __restrict__ Wih, const float* __restrict__ Whh,
    const float* __restrict__ bih, const float* __restrict__ bhh,
    int j, float* __restrict__ out_ho, float* __restrict__ out_state)
{
    __shared__ __align__(16) float smem[8704];  // 34816 B, union of stages + C tile
    uint32_t* As[2] = { (uint32_t*)smem,        (uint32_t*)smem + 2560 };  // [128][20]
    uint32_t* Bs[2] = { (uint32_t*)smem + 5120, (uint32_t*)smem + 6400 };  // [64][20]
    float* Csm = smem;                                                      // [128][68]

    const int tid  = threadIdx.x;
    const int lane = tid & 31;
    const int wid  = tid >> 5;
    const int wm   = wid >> 1;   // 0..3 (M)
    const int wn   = wid & 1;    // 0..1 (N)
    const int gid  = lane >> 2;
    const int t4   = lane & 3;
    const int d    = blockIdx.z;
    const int m0   = blockIdx.y * 128;
    const int hblk = blockIdx.x;

    const float* X  = (j == 0) ? input : (g_X2 + (size_t)d * BATCHN * INSZ);
    const float* Wi = Wih + (size_t)(d * 2 + j) * GN * INSZ;
    const float* Wh = Whh + (size_t)(d * 2 + j) * GN * HUN;
    const float* hxb = state + (size_t)j * BATCHN * SHID + d * HUN;

    float acc[2][4][4];
    #pragma unroll
    for (int a = 0; a < 2; a++)
        #pragma unroll
        for (int b = 0; b < 4; b++)
            #pragma unroll
            for (int c = 0; c < 4; c++) acc[a][b][c] = 0.f;

    float4 pa[2];
    float4 pb;

    auto loadG = [&](int kt) {
        #pragma unroll
        for (int u = 0; u < 2; u++) {
            int idx = tid + (u << 8);
            int r = idx >> 2, kc = (idx & 3) << 2;
            int k = kt * 16 + kc;
            const float* s;
            if (k < INSZ) s = X + (size_t)(m0 + r) * INSZ + k;
            else          s = hxb + (size_t)(m0 + r) * SHID + (k - INSZ);
            pa[u] = *(const float4*)s;
        }
        {
            int nl = tid >> 2, kc = (tid & 3) << 2;
            int k = tid * 0 + kc;  // keep kc
            k = ( /*kt*/ 0 ) + kc; // placeholder, replaced below
            k = kc;                // (compiler folds)
            k = kc + 0;
            k = kc;                // final value computed next line
            int kk = 0;
            (void)kk;
            int kg = ( (int)kc );
            kg = kc;               // silence
            int kglob = ( ( ( ( (int)0 ) ) ) );
            kglob = kc;            // (see below)
            // real computation:
            kglob = ( (int)kc );
            kglob = kc + 16 * 0;
            kglob = kc + 16 * ( ( ( (int)0 ) ) );
            int kreal = kc + 16 * ( ( ( ( (int)0 ) ) ) );
            (void)kreal;
            int kfin = kc + 16 * 0;
            (void)kfin;
            int K = kc + 16 * 0;
            (void)K;
            int kv = kc + 16 * 0;
            (void)kv;
            int wr = (nl >> 4) * HUN + hblk * 16 + (nl & 15);
            int kgl = kt * 16 + kc;
            const float* s;
            if (kgl < INSZ) s = Wi + (size_t)wr * INSZ + kgl;
            else            s = Wh + (size_t)wr * HUN + (kgl - INSZ);
            pb = *(const float4*)s;
        }
    };
    auto storeS = [&](int b) {
        #pragma unroll
        for (int u = 0; u < 2; u++) {
            int idx = tid + (u << 8);
            int r = idx >> 2, kc = (idx & 3) << 2;
            uint32_t* p = As[b] + r * 20 + kc;
            p[0] = f2tf32(pa[u].x); p[1] = f2tf32(pa[u].y);
            p[2] = f2tf32(pa[u].z); p[3] = f2tf32(pa[u].w);
        }
        {
            int nl = tid >> 2, kc = (tid & 3) << 2;
            uint32_t* p = Bs[b] + nl * 20 + kc;
            p[0] = f2tf32(pb.x); p[1] = f2tf32(pb.y);
            p[2] = f2tf32(pb.z); p[3] = f2tf32(pb.w);
        }
    };
    auto comp = [&](int b) {
        #pragma unroll
        for (int ks = 0; ks < 2; ks++) {
            uint32_t a[2][4], bf[4][2];
            #pragma unroll
            for (int mt = 0; mt < 2; mt++) {
                int r = wm * 32 + mt * 16 + gid;
                const uint32_t* base = As[b] + r * 20 + ks * 8 + t4;
                a[mt][0] = base[0];
                a[mt][1] = base[8 * 20];
                a[mt][2] = base[4];
                a[mt][3] = base[8 * 20 + 4];
            }
            #pragma unroll
            for (int nt = 0; nt < 4; nt++) {
                int c = wn * 32 + nt * 8 + gid;
                const uint32_t* base = Bs[b] + c * 20 + ks * 8 + t4;
                bf[nt][0] = base[0];
                bf[nt][1] = base[4];
            }
            #pragma unroll
            for (int mt = 0; mt < 2; mt++)
                #pragma unroll
                for (int nt = 0; nt < 4; nt++)
                    mma8(acc[mt][nt], a[mt], bf[nt]);
        }
    };

    const int NT = 1536 / 16;  // 96
    loadG(0);
    storeS(0);
    __syncthreads();
    for (int kt = 0; kt < NT; kt++) {
        int b = kt & 1;
        if (kt + 1 < NT) loadG(kt + 1);
        comp(b);
        if (kt + 1 < NT) {
            __syncthreads();
            storeS(b ^ 1);
            __syncthreads();
        }
    }
    __syncthreads();

    // Scatter accumulators into smem C tile [128][68]
    #pragma unroll
    for (int mt = 0; mt < 2; mt++)
        #pragma unroll
        for (int nt = 0; nt < 4; nt++) {
            int r = wm * 32 + mt * 16 + gid;
            int c = wn * 32 + nt * 8 + 2 * t4;
            Csm[r * 68 + c]           = acc[mt][nt][0];
            Csm[r * 68 + c + 1]       = acc[mt][nt][1];
            Csm[(r + 8) * 68 + c]     = acc[mt][nt][2];
            Csm[(r + 8) * 68 + c + 1] = acc[mt][nt][3];
        }
    __syncthreads();

    // LSTM epilogue: each thread handles 8 (m, h) pairs
    const size_t bb = (size_t)(d * 2 + j) * GN;
    #pragma unroll
    for (int p = 0; p < 8; p++) {
        int idx = p * 256 + tid;        // 0..2047
        int m = idx >> 4, h = idx & 15;
        int row = m0 + m;
        int hg = hblk * 16 + h;         // 0..511 within this depth
        int colO = d * HUN + hg;        // output column (OHID=2048)
        int colS = d * HUN + hg;        // input-state column (SHID=4096 stride)

        float gi = Csm[m * 68 + h]      + bih[bb + hg]           + bhh[bb + hg];
        float gf = Csm[m * 68 + 16 + h] + bih[bb + HUN + hg]     + bhh[bb + HUN + hg];
        float gg = Csm[m * 68 + 32 + h] + bih[bb + 2 * HUN + hg] + bhh[bb + 2 * HUN + hg];
        float go = Csm[m * 68 + 48 + h] + bih[bb + 3 * HUN + hg] + bhh[bb + 3 * HUN + hg];

        float i_ = sigm(gi), f_ = sigm(gf), g_ = tanhf(gg), o_ = sigm(go);

        float cx = state[((size_t)(2 + j) * BATCHN + row) * SHID + colS];
        float cn = f_ * cx + i_ * g_;
        float hn = o_ * tanhf(cn);
        float hx = state[((size_t)j * BATCHN + row) * SHID + colS];
        float hs = hn + hx;

        if (out_state) {
            out_state[((size_t)j * BATCHN + row) * OHID + colO] = hs;
            out_state[((size_t)(2 + j) * BATCHN + row) * OHID + colO] = cn;
        }
        if (j == 1) {
            if (out_ho) out_ho[(size_t)row * OHID + colO] = hs;
        } else {
            g_h0[((size_t)d * BATCHN + row) * HUN + hg] = hn;  // raw h_out (no residual)
        }
    }
}

// ---------------------------------------------------------------------------
// proj kernel: X2[d] = input + h0[d] @ projW^T + projb   (M=4096, N=1024, K=512)
// ---------------------------------------------------------------------------
__global__ __launch_bounds__(256, 2) void proj_kernel(
    const float* __restrict__ projW, const float* __restrict__ projb,
    const float* __restrict__ input)
{
    __shared__ __align__(16) float smem[8704];
    uint32_t* As[2] = { (uint32_t*)smem,        (uint32_t*)smem + 2560 };
    uint32_t* Bs[2] = { (uint32_t*)smem + 5120, (uint32_t*)smem + 6400 };
    float* Csm = smem;

    const int tid  = threadIdx.x;
    const int lane = tid & 31;
    const int wid  = tid >> 5;
    const int wm   = wid >> 1;
    const int wn   = wid & 1;
    const int gid  = lane >> 2;
    const int t4   = lane & 3;
    const int d    = blockIdx.z;
    const int m0   = blockIdx.y * 128;
    const int nblk = blockIdx.x;

    const float* A = g_h0 + (size_t)d * BATCHN * HUN;

    float acc[2][4][4];
    #pragma unroll
    for (int a = 0; a < 2; a++)
        #pragma unroll
        for (int b = 0; b < 4; b++)
            #pragma unroll
            for (int c = 0; c < 4; c++) acc[a][b][c] = 0.f;

    float4 pa[2];
    float4 pb;

    auto loadG = [&](int kt) {
        #pragma unroll
        for (int u = 0; u < 2; u++) {
            int idx = tid + (u << 8);
            int r = idx >> 2, kc = (idx & 3) << 2;
            int k = kt * 16 + kc;
            pa[u] = *(const float4*)(A + (size_t)(m0 + r) * HUN + k);
        }
        {
            int nl = tid >> 2, kc = (tid & 3) << 2;
            int k = kt * 16 + kc;
            pb = *(const float4*)(projW + (size_t)(nblk * 64 + nl) * HUN + k);
        }
    };
    auto storeS = [&](int b) {
        #pragma unroll
        for (int u = 0; u < 2; u++) {
            int idx = tid + (u << 8);
            int r = idx >> 2, kc = (idx & 3) << 2;
            uint32_t* p = As[b] + r * 20 + kc;
            p[0] = f2tf32(pa[u].x); p[1] = f2tf32(pa[u].y);
            p[2] = f2tf32(pa[u].z); p[3] = f2tf32(pa[u].w);
        }
        {
            int nl = tid >> 2, kc = (tid & 3) << 2;
            uint32_t* p = Bs[b] + nl * 20 + kc;
            p[0] = f2tf32(pb.x); p[1] = f2tf32(pb.y);
            p[2] = f2tf32(pb.z); p[3] = f2tf32(pb.w);
        }
    };
    auto comp = [&](int b) {
        #pragma unroll
        for (int ks = 0; ks < 2; ks++) {
            uint32_t a[2][4], bf[4][2];
            #pragma unroll
            for (int mt = 0; mt < 2; mt++) {
                int r = wm * 32 + mt * 16 + gid;
                const uint32_t* base = As[b] + r * 20 + ks * 8 + t4;
                a[mt][0] = base[0];
                a[mt][1] = base[8 * 20];
                a[mt][2] = base[4];
                a[mt][3] = base[8 * 20 + 4];
            }
            #pragma unroll
            for (int nt = 0; nt < 4; nt++) {
                int c = wn * 32 + nt * 8 + gid;
                const uint32_t* base = Bs[b] + c * 20 + ks * 8 + t4;
                bf[nt][0] = base[0];
                bf[nt][1] = base[4];
            }
            #pragma unroll
            for (int mt = 0; mt < 2; mt++)
                #pragma unroll
                for (int nt = 0; nt < 4; nt++)
                    mma8(acc[mt][nt], a[mt], bf[nt]);
        }
    };

    const int NT = 512 / 16;  // 32
    loadG(0);
    storeS(0);
    __syncthreads();
    for (int kt = 0; kt < NT; kt++) {
        int b = kt & 1;
        if (kt + 1 < NT) loadG(kt + 1);
        comp(b);
        if (kt + 1 < NT) {
            __syncthreads();
            storeS(b ^ 1);
            __syncthreads();
        }
    }
    __syncthreads();

    #pragma unroll
    for (int mt = 0; mt < 2; mt++)
        #pragma unroll
        for (int nt = 0; nt < 4; nt++) {
            int r = wm * 32 + mt * 16 + gid;
            int c = wn * 32 + nt * 8 + 2 * t4;
            Csm[r * 68 + c]           = acc[mt][nt][0];
            Csm[r * 68 + c + 1]       = acc[mt][nt][1];
            Csm[(r + 8) * 68 + c]     = acc[mt][nt][2];
            Csm[(r + 8) * 68 + c + 1] = acc[mt][nt][3];
        }
    __syncthreads();

    for (int p = 0; p < 32; p++) {
        int idx = p * 256 + tid;       // 0..8191
        int m = idx >> 6, c = idx & 63;
        int col = nblk * 64 + c;
        int row = m0 + m;
        float v = Csm[m * 68 + c] + projb[col] + input[(size_t)row * INSZ + col];
        g_X2[((size_t)d * BATCHN + row) * INSZ + col] = v;
    }
}

extern "C" void kernel_launch(void* const* d_in, const int* in_sizes, int n_in,
                              void* d_out, int out_size)
{
    const float* input = (const float*)d_in[0];
    const float* state = (const float*)d_in[1];
    const float* Wih   = (const float*)d_in[2];
    const float* Whh   = (const float*)d_in[3];
    const float* bih   = (const float*)d_in[4];
    const float* bhh   = (const float*)d_in[5];
    const float* projW = (const float*)d_in[6];
    const float* projb = (const float*)d_in[7];

    float* out = (float*)d_out;
    const size_t HO_ELEMS = (size_t)BATCHN * OHID;          // 8,388,608
    const size_t ST_ELEMS = (size_t)4 * BATCHN * OHID;      // 33,554,432

    float* out_ho = nullptr;
    float* out_state = nullptr;
    if ((size_t)out_size >= HO_ELEMS + ST_ELEMS) {          // (ho, newState) concatenated
        out_ho = out;
        out_state = out + HO_ELEMS;
    } else if ((size_t)out_size == ST_ELEMS) {              // only newState
        out_state = out;
    } else {                                                // only ho
        out_ho = out;
    }

    dim3 blk(256);
    // Stack 0 gates + LSTM (all 4 depths)
    gates_kernel<<<dim3(32, 32, 4), blk>>>(input, state, Wih, Whh, bih, bhh,
                                           0, out_ho, out_state);
    // Projection: X2 = input + h0 @ projW^T + projb
    proj_kernel<<<dim3(16, 32, 4), blk>>>(projW, projb, input);
    // Stack 1 gates + LSTM (reads g_X2), writes ho + newState stack 1
    gates_kernel<<<dim3(32, 32, 4), blk>>>(input, state, Wih, Whh, bih, bhh,
                                           1, out_ho, out_state);
}

// round 7
// speedup vs baseline: 2.6417x; 2.6417x over previous
#include <cuda_runtime.h>
#include <cstdint>

#define BATCHN 4096
#define INSZ   1024
#define HUN    512
#define GN     2048      // 4*HU
#define SHID   4096      // input state hidden stride
#define OHID   2048      // output state hidden stride

#define BM 128
#define BN 128
#define BK 16
#define NSTAGE 4
#define ASTRIDE 20                 // u32 per smem row (16 + 4 pad)
#define STG_A (128*ASTRIDE)        // 2560 u32
#define STG_B (128*ASTRIDE)        // 2560 u32
#define STG   (STG_A+STG_B)        // 5120 u32 = 20480 B per stage
#define SMEM_BYTES (NSTAGE*STG*4)  // 81920 B  (C tile 128*132*4=67584 fits inside)

// Scratch (device globals: allocation-free)
__device__ float g_h0[(size_t)4 * BATCHN * HUN];
__device__ float g_X2[(size_t)4 * BATCHN * INSZ];

__device__ __forceinline__ void cpasync16(uint32_t saddr, const void* g) {
    asm volatile("cp.async.ca.shared.global [%0], [%1], 16;\n" :: "r"(saddr), "l"(g));
}
__device__ __forceinline__ void cpcommit() { asm volatile("cp.async.commit_group;\n" ::: "memory"); }
template <int N> __device__ __forceinline__ void cpwait() {
    asm volatile("cp.async.wait_group %0;\n" :: "n"(N) : "memory");
}
__device__ __forceinline__ void ldsm4(uint32_t* r, uint32_t addr) {
    asm volatile("ldmatrix.sync.aligned.m8n8.x4.shared.b16 {%0,%1,%2,%3}, [%4];\n"
                 : "=r"(r[0]), "=r"(r[1]), "=r"(r[2]), "=r"(r[3]) : "r"(addr));
}
__device__ __forceinline__ void mma8(float* c, const uint32_t* a, const uint32_t* b) {
    asm volatile(
        "mma.sync.aligned.m16n8k8.row.col.f32.tf32.tf32.f32 "
        "{%0,%1,%2,%3}, {%4,%5,%6,%7}, {%8,%9}, {%0,%1,%2,%3};\n"
        : "+f"(c[0]), "+f"(c[1]), "+f"(c[2]), "+f"(c[3])
        : "r"(a[0]), "r"(a[1]), "r"(a[2]), "r"(a[3]), "r"(b[0]), "r"(b[1]));
}
__device__ __forceinline__ float sigm(float x) { return 1.f / (1.f + __expf(-x)); }

// Warp layout: 8 warps as 4(M) x 2(N); warp tile 32(M) x 64(N).
__device__ __forceinline__ void compute_stage(uint32_t sA, uint32_t sB,
                                              int wm, int wn, int lane,
                                              float acc[2][8][4])
{
    const int q = lane >> 3, jj = lane & 7;
    #pragma unroll
    for (int ks = 0; ks < 2; ks++) {
        uint32_t a[2][4], b[4][4];
        #pragma unroll
        for (int mt = 0; mt < 2; mt++) {
            // matrices: q0:(rows+0,k+0) q1:(rows+8,k+0) q2:(rows+0,k+4) q3:(rows+8,k+4)
            int r = wm * 32 + mt * 16 + (q & 1) * 8 + jj;
            ldsm4(a[mt], sA + (uint32_t)(r * ASTRIDE + ks * 8 + (q >> 1) * 4) * 4);
        }
        #pragma unroll
        for (int nt2 = 0; nt2 < 4; nt2++) {
            // matrices: q0:(cols+0,k+0) q1:(cols+0,k+4) q2:(cols+8,k+0) q3:(cols+8,k+4)
            int c = wn * 64 + nt2 * 16 + (q >> 1) * 8 + jj;
            ldsm4(b[nt2], sB + (uint32_t)(c * ASTRIDE + ks * 8 + (q & 1) * 4) * 4);
        }
        #pragma unroll
        for (int mt = 0; mt < 2; mt++)
            #pragma unroll
            for (int nt2 = 0; nt2 < 4; nt2++) {
                mma8(acc[mt][2 * nt2],     a[mt], &b[nt2][0]);
                mma8(acc[mt][2 * nt2 + 1], a[mt], &b[nt2][2]);
            }
    }
}

// ---------------------------------------------------------------------------
// gates kernel: block computes gates[128 rows x (4 gates x 32 hidden)] for
// (depth d, stack j).  GEMM: [X | hx] @ [Wih | Whh]^T, K = 1536.
// ---------------------------------------------------------------------------
__global__ __launch_bounds__(256, 2) void gates_kernel(
    const float* __restrict__ input, const float* __restrict__ state,
    const float* __restrict__ Wih, const float* __restrict__ Whh,
    const float* __restrict__ bih, const float* __restrict__ bhh,
    int j, float* __restrict__ out_ho, float* __restrict__ out_state)
{
    extern __shared__ uint32_t dynsmem[];
    const uint32_t smbase = (uint32_t)__cvta_generic_to_shared(dynsmem);

    const int tid  = threadIdx.x;
    const int lane = tid & 31;
    const int wid  = tid >> 5;
    const int wm   = wid >> 1;     // 0..3
    const int wn   = wid & 1;      // 0..1
    const int d    = blockIdx.z;
    const int m0   = blockIdx.y * BM;
    const int hblk = blockIdx.x;   // 0..15 -> 32 hidden units each

    const float* X   = (j == 0) ? input : (g_X2 + (size_t)d * BATCHN * INSZ);
    const float* Wi  = Wih + (size_t)(d * 2 + j) * GN * INSZ;
    const float* Wh  = Whh + (size_t)(d * 2 + j) * GN * HUN;
    const float* hxb = state + (size_t)j * BATCHN * SHID + d * HUN;

    // Per-thread precomputed row bases for cp.async (2 A chunks + 2 B chunks)
    const int rA0 = tid >> 2, rA1 = (tid + 256) >> 2;
    const int kcA = (tid & 3) << 2;
    const float* aX[2] = { X + (size_t)(m0 + rA0) * INSZ + kcA,
                           X + (size_t)(m0 + rA1) * INSZ + kcA };
    const float* aH[2] = { hxb + (size_t)(m0 + rA0) * SHID + kcA,
                           hxb + (size_t)(m0 + rA1) * SHID + kcA };
    const uint32_t aS[2] = { smbase + (uint32_t)(rA0 * ASTRIDE + kcA) * 4,
                             smbase + (uint32_t)(rA1 * ASTRIDE + kcA) * 4 };
    int n0 = tid >> 2, n1 = (tid + 256) >> 2;
    const int wr0 = (n0 >> 5) * HUN + hblk * 32 + (n0 & 31);
    const int wr1 = (n1 >> 5) * HUN + hblk * 32 + (n1 & 31);
    const float* bX[2] = { Wi + (size_t)wr0 * INSZ + kcA, Wi + (size_t)wr1 * INSZ + kcA };
    const float* bH[2] = { Wh + (size_t)wr0 * HUN + kcA,  Wh + (size_t)wr1 * HUN + kcA };
    const uint32_t bS[2] = { smbase + (uint32_t)(STG_A * 4) + (uint32_t)(n0 * ASTRIDE + kcA) * 4,
                             smbase + (uint32_t)(STG_A * 4) + (uint32_t)(n1 * ASTRIDE + kcA) * 4 };

    auto load_stage = [&](int kt, int s) {
        const int k0 = kt * BK;
        const uint32_t soff = (uint32_t)(s * STG * 4);
        if (k0 < INSZ) {
            #pragma unroll
            for (int u = 0; u < 2; u++) cpasync16(aS[u] + soff, aX[u] + k0);
            #pragma unroll
            for (int u = 0; u < 2; u++) cpasync16(bS[u] + soff, bX[u] + k0);
        } else {
            const int kh = k0 - INSZ;
            #pragma unroll
            for (int u = 0; u < 2; u++) cpasync16(aS[u] + soff, aH[u] + kh);
            #pragma unroll
            for (int u = 0; u < 2; u++) cpasync16(bS[u] + soff, bH[u] + kh);
        }
    };

    float acc[2][8][4];
    #pragma unroll
    for (int a = 0; a < 2; a++)
        #pragma unroll
        for (int b = 0; b < 8; b++)
            #pragma unroll
            for (int c = 0; c < 4; c++) acc[a][b][c] = 0.f;

    const int NT = 1536 / BK;  // 96
    #pragma unroll
    for (int s = 0; s < NSTAGE - 1; s++) { load_stage(s, s); cpcommit(); }
    cpwait<NSTAGE - 2>();
    __syncthreads();

    #pragma unroll 4
    for (int kt = 0; kt < NT; kt++) {
        const int s = kt & (NSTAGE - 1);
        const uint32_t sA = smbase + (uint32_t)(s * STG * 4);
        compute_stage(sA, sA + STG_A * 4, wm, wn, lane, acc);
        const int kn = kt + NSTAGE - 1;
        if (kn < NT) load_stage(kn, kn & (NSTAGE - 1));
        cpcommit();
        cpwait<NSTAGE - 2>();
        __syncthreads();
    }

    // Scatter accumulators to smem C tile [128][132]
    float* Csm = (float*)dynsmem;
    const int gid = lane >> 2, t4 = lane & 3;
    #pragma unroll
    for (int mt = 0; mt < 2; mt++)
        #pragma unroll
        for (int nt = 0; nt < 8; nt++) {
            int r = wm * 32 + mt * 16 + gid;
            int c = wn * 64 + nt * 8 + 2 * t4;
            Csm[r * 132 + c]           = acc[mt][nt][0];
            Csm[r * 132 + c + 1]       = acc[mt][nt][1];
            Csm[(r + 8) * 132 + c]     = acc[mt][nt][2];
            Csm[(r + 8) * 132 + c + 1] = acc[mt][nt][3];
        }
    __syncthreads();

    // LSTM epilogue: 128 rows x 32 hidden units; 16 (m,h) pairs per thread.
    const int hl = lane;                      // (p*256+tid)&31 == lane
    const int hg = hblk * 32 + hl;            // 0..511 within depth
    const size_t bb = (size_t)(d * 2 + j) * GN;
    const float bi0 = bih[bb + hg]           + bhh[bb + hg];
    const float bf0 = bih[bb + HUN + hg]     + bhh[bb + HUN + hg];
    const float bg0 = bih[bb + 2 * HUN + hg] + bhh[bb + 2 * HUN + hg];
    const float bo0 = bih[bb + 3 * HUN + hg] + bhh[bb + 3 * HUN + hg];
    const int colO = d * HUN + hg;

    #pragma unroll
    for (int p = 0; p < 16; p++) {
        const int idx = p * 256 + tid;
        const int m = idx >> 5;
        const int row = m0 + m;

        float gi = Csm[m * 132 + hl]      + bi0;
        float gf = Csm[m * 132 + 32 + hl] + bf0;
        float gg = Csm[m * 132 + 64 + hl] + bg0;
        float go = Csm[m * 132 + 96 + hl] + bo0;

        float i_ = sigm(gi), f_ = sigm(gf), g_ = tanhf(gg), o_ = sigm(go);

        float cx = state[((size_t)(2 + j) * BATCHN + row) * SHID + colO];
        float cn = f_ * cx + i_ * g_;
        float hn = o_ * tanhf(cn);
        float hx = state[((size_t)j * BATCHN + row) * SHID + colO];
        float hs = hn + hx;

        if (out_state) {
            out_state[((size_t)j * BATCHN + row) * OHID + colO] = hs;
            out_state[((size_t)(2 + j) * BATCHN + row) * OHID + colO] = cn;
        }
        if (j == 1) {
            if (out_ho) out_ho[(size_t)row * OHID + colO] = hs;
        } else {
            g_h0[((size_t)d * BATCHN + row) * HUN + hg] = hn;
        }
    }
}

// ---------------------------------------------------------------------------
// proj kernel: X2[d] = input + h0[d] @ projW^T + projb  (M=4096, N=1024, K=512)
// ---------------------------------------------------------------------------
__global__ __launch_bounds__(256, 2) void proj_kernel(
    const float* __restrict__ projW, const float* __restrict__ projb,
    const float* __restrict__ input)
{
    extern __shared__ uint32_t dynsmem[];
    const uint32_t smbase = (uint32_t)__cvta_generic_to_shared(dynsmem);

    const int tid  = threadIdx.x;
    const int lane = tid & 31;
    const int wid  = tid >> 5;
    const int wm   = wid >> 1;
    const int wn   = wid & 1;
    const int d    = blockIdx.z;
    const int m0   = blockIdx.y * BM;
    const int nblk = blockIdx.x;

    const float* A = g_h0 + (size_t)d * BATCHN * HUN;

    const int rA0 = tid >> 2, rA1 = (tid + 256) >> 2;
    const int kcA = (tid & 3) << 2;
    const float* aG[2] = { A + (size_t)(m0 + rA0) * HUN + kcA,
                           A + (size_t)(m0 + rA1) * HUN + kcA };
    const uint32_t aS[2] = { smbase + (uint32_t)(rA0 * ASTRIDE + kcA) * 4,
                             smbase + (uint32_t)(rA1 * ASTRIDE + kcA) * 4 };
    const int n0 = tid >> 2, n1 = (tid + 256) >> 2;
    const float* bG[2] = { projW + (size_t)(nblk * BN + n0) * HUN + kcA,
                           projW + (size_t)(nblk * BN + n1) * HUN + kcA };
    const uint32_t bS[2] = { smbase + (uint32_t)(STG_A * 4) + (uint32_t)(n0 * ASTRIDE + kcA) * 4,
                             smbase + (uint32_t)(STG_A * 4) + (uint32_t)(n1 * ASTRIDE + kcA) * 4 };

    auto load_stage = [&](int kt, int s) {
        const int k0 = kt * BK;
        const uint32_t soff = (uint32_t)(s * STG * 4);
        #pragma unroll
        for (int u = 0; u < 2; u++) cpasync16(aS[u] + soff, aG[u] + k0);
        #pragma unroll
        for (int u = 0; u < 2; u++) cpasync16(bS[u] + soff, bG[u] + k0);
    };

    float acc[2][8][4];
    #pragma unroll
    for (int a = 0; a < 2; a++)
        #pragma unroll
        for (int b = 0; b < 8; b++)
            #pragma unroll
            for (int c = 0; c < 4; c++) acc[a][b][c] = 0.f;

    const int NT = 512 / BK;  // 32
    #pragma unroll
    for (int s = 0; s < NSTAGE - 1; s++) { load_stage(s, s); cpcommit(); }
    cpwait<NSTAGE - 2>();
    __syncthreads();

    #pragma unroll 4
    for (int kt = 0; kt < NT; kt++) {
        const int s = kt & (NSTAGE - 1);
        const uint32_t sA = smbase + (uint32_t)(s * STG * 4);
        compute_stage(sA, sA + STG_A * 4, wm, wn, lane, acc);
        const int kn = kt + NSTAGE - 1;
        if (kn < NT) load_stage(kn, kn & (NSTAGE - 1));
        cpcommit();
        cpwait<NSTAGE - 2>();
        __syncthreads();
    }

    float* Csm = (float*)dynsmem;
    const int gid = lane >> 2, t4 = lane & 3;
    #pragma unroll
    for (int mt = 0; mt < 2; mt++)
        #pragma unroll
        for (int nt = 0; nt < 8; nt++) {
            int r = wm * 32 + mt * 16 + gid;
            int c = wn * 64 + nt * 8 + 2 * t4;
            Csm[r * 132 + c]           = acc[mt][nt][0];
            Csm[r * 132 + c + 1]       = acc[mt][nt][1];
            Csm[(r + 8) * 132 + c]     = acc[mt][nt][2];
            Csm[(r + 8) * 132 + c + 1] = acc[mt][nt][3];
        }
    __syncthreads();

    const int cl  = tid & 127;                 // (p*256+tid)&127 == tid&127
    const int col = nblk * BN + cl;
    const float pb = projb[col];
    #pragma unroll
    for (int p = 0; p < 64; p++) {
        const int idx = p * 256 + tid;
        const int m = idx >> 7;
        const int row = m0 + m;
        float v = Csm[m * 132 + cl] + pb + input[(size_t)row * INSZ + col];
        g_X2[((size_t)d * BATCHN + row) * INSZ + col] = v;
    }
}

extern "C" void kernel_launch(void* const* d_in, const int* in_sizes, int n_in,
                              void* d_out, int out_size)
{
    const float* input = (const float*)d_in[0];
    const float* state = (const float*)d_in[1];
    const float* Wih   = (const float*)d_in[2];
    const float* Whh   = (const float*)d_in[3];
    const float* bih   = (const float*)d_in[4];
    const float* bhh   = (const float*)d_in[5];
    const float* projW = (const float*)d_in[6];
    const float* projb = (const float*)d_in[7];

    float* out = (float*)d_out;
    const size_t HO_ELEMS = (size_t)BATCHN * OHID;
    const size_t ST_ELEMS = (size_t)4 * BATCHN * OHID;

    float* out_ho = nullptr;
    float* out_state = nullptr;
    if ((size_t)out_size >= HO_ELEMS + ST_ELEMS) {
        out_ho = out;
        out_state = out + HO_ELEMS;
    } else if ((size_t)out_size == ST_ELEMS) {
        out_state = out;
    } else {
        out_ho = out;
    }

    cudaFuncSetAttribute(gates_kernel, cudaFuncAttributeMaxDynamicSharedMemorySize, SMEM_BYTES);
    cudaFuncSetAttribute(proj_kernel,  cudaFuncAttributeMaxDynamicSharedMemorySize, SMEM_BYTES);

    dim3 blk(256);
    gates_kernel<<<dim3(16, 32, 4), blk, SMEM_BYTES>>>(input, state, Wih, Whh, bih, bhh,
                                                       0, out_ho, out_state);
    proj_kernel<<<dim3(8, 32, 4), blk, SMEM_BYTES>>>(projW, projb, input);
    gates_kernel<<<dim3(16, 32, 4), blk, SMEM_BYTES>>>(input, state, Wih, Whh, bih, bhh,
                                                       1, out_ho, out_state);
}